// round 3
// baseline (speedup 1.0000x reference)
#include <cuda_runtime.h>

#define Bn 4
#define Cn 256
#define Hn 128
#define Wn 128
#define N_ROIS 512
#define Pn 7
#define SCALE_F 0.0625f
#define GAMMA_F 0.1f

// NHWC scratch: [B, H, W, C] = 16,777,216 floats (64 MB)
__device__ float g_xt[Bn * Hn * Wn * Cn];

// ---------------------------------------------------------------------------
// NCHW -> NHWC transpose, float4 both directions.
// ---------------------------------------------------------------------------
__global__ void __launch_bounds__(256) transpose_nchw_nhwc(const float* __restrict__ x) {
    __shared__ float tile[32][33];
    const int bhy = blockIdx.z;          // b*H + y
    const int b = bhy >> 7;
    const int y = bhy & 127;
    const int w0 = blockIdx.x * 32;
    const int tid = threadIdx.x;

    const int cl = tid >> 3;             // 0..31 channel row (load)
    const int w4 = (tid & 7) * 4;        // 0..28 w quad (load)
    const int wl = tid >> 3;             // 0..31 w (store)
    const int c4 = (tid & 7) * 4;        // 0..28 c quad (store)

#pragma unroll
    for (int ct = 0; ct < 4; ct++) {
        const int c0 = blockIdx.y * 128 + ct * 32;
        const float4 v = *(const float4*)(x + (((size_t)(b * Cn + c0 + cl) * Hn + y) * Wn + w0 + w4));
        tile[cl][w4 + 0] = v.x;
        tile[cl][w4 + 1] = v.y;
        tile[cl][w4 + 2] = v.z;
        tile[cl][w4 + 3] = v.w;
        __syncthreads();
        float4 o;
        o.x = tile[c4 + 0][wl];
        o.y = tile[c4 + 1][wl];
        o.z = tile[c4 + 2][wl];
        o.w = tile[c4 + 3][wl];
        *(float4*)(g_xt + ((size_t)(bhy * Wn + w0 + wl) * Cn + c0 + c4)) = o;
        __syncthreads();
    }
}

// ---------------------------------------------------------------------------
// Deformable ROI pool. Grid (512, 2): blockIdx.x = ROI, blockIdx.y = channel
// half (0: ch 0-127, 1: ch 128-255). 256 threads = 32 channel-quads x 8 bin
// slices. ~30KB smem -> 7 CTAs/SM -> ALL 1024 CTAs resident in one wave.
// ---------------------------------------------------------------------------
#define SOUT_PITCH 132   // 128 floats/row + 4 pad (16B-aligned rows)

__global__ void __launch_bounds__(256, 7) dcn_pool_kernel(
    const float* __restrict__ rois,
    const float* __restrict__ offset,
    float* __restrict__ out)
{
    extern __shared__ float smem[];
    float* s_out = smem;                           // 49*132 = 6468 floats
    float* s_w   = smem + 49 * SOUT_PITCH;         // 49*16  = 784 floats
    int*   s_off = (int*)(s_w + 49 * 16);          // 49*8   = 392 ints

    const int n    = blockIdx.x;
    const int half = blockIdx.y;
    const int tid  = threadIdx.x;

    const int bidx = (int)rois[n * 5 + 0];

    if (tid < 49) {
        const float x1 = rois[n * 5 + 1] * SCALE_F - 0.5f;
        const float y1 = rois[n * 5 + 2] * SCALE_F - 0.5f;
        const float x2 = rois[n * 5 + 3] * SCALE_F - 0.5f;
        const float y2 = rois[n * 5 + 4] * SCALE_F - 0.5f;
        const float rw = fmaxf(x2 - x1, 1.0f);
        const float rh = fmaxf(y2 - y1, 1.0f);
        const float bw = rw * (1.0f / Pn);
        const float bh = rh * (1.0f / Pn);

        const int ph = tid / 7;
        const int pw = tid - ph * 7;
        const float ox = offset[n * 98 + tid];
        const float oy = offset[n * 98 + 49 + tid];
        const float ybase = y1 + (float)ph * bh + GAMMA_F * rh * oy;
        const float xbase = x1 + (float)pw * bw + GAMMA_F * rw * ox;

        // ---- y direction: 4 samples -> weights over 4 contiguous rows ----
        float wy[4] = {0.f, 0.f, 0.f, 0.f};
        int   y0a[4];
        float lya[4], va[4];
        int rmin = Hn;
#pragma unroll
        for (int i = 0; i < 4; i++) {
            const float s  = ((float)i + 0.5f) * 0.25f;
            const float ys = ybase + s * bh;
            const float v  = (ys > -1.0f && ys < (float)Hn) ? 0.25f : 0.0f;
            const float yc = fminf(fmaxf(ys, 0.0f), (float)(Hn - 1));
            const int   y0 = (int)yc;
            y0a[i] = y0; lya[i] = yc - (float)y0; va[i] = v;
            rmin = min(rmin, y0);
        }
#pragma unroll
        for (int i = 0; i < 4; i++) {
            const int sl0 = min(y0a[i] - rmin, 3);
            const int sl1 = min(min(y0a[i] + 1, Hn - 1) - rmin, 3);
            wy[sl0] += (1.0f - lya[i]) * va[i];
            wy[sl1] += lya[i] * va[i];
        }

        // ---- x direction ----
        float wx[4] = {0.f, 0.f, 0.f, 0.f};
        int   x0a[4];
        float lxa[4], vxa[4];
        int cmin = Wn;
#pragma unroll
        for (int j = 0; j < 4; j++) {
            const float s  = ((float)j + 0.5f) * 0.25f;
            const float xs = xbase + s * bw;
            const float v  = (xs > -1.0f && xs < (float)Wn) ? 0.25f : 0.0f;
            const float xc = fminf(fmaxf(xs, 0.0f), (float)(Wn - 1));
            const int   x0 = (int)xc;
            x0a[j] = x0; lxa[j] = xc - (float)x0; vxa[j] = v;
            cmin = min(cmin, x0);
        }
#pragma unroll
        for (int j = 0; j < 4; j++) {
            const int sl0 = min(x0a[j] - cmin, 3);
            const int sl1 = min(min(x0a[j] + 1, Wn - 1) - cmin, 3);
            wx[sl0] += (1.0f - lxa[j]) * vxa[j];
            wx[sl1] += lxa[j] * vxa[j];
        }

        // ---- weights (16) + row/col offsets (4+4) ----
#pragma unroll
        for (int r = 0; r < 4; r++)
#pragma unroll
            for (int q = 0; q < 4; q++)
                s_w[tid * 16 + r * 4 + q] = wy[r] * wx[q];
#pragma unroll
        for (int k = 0; k < 4; k++) {
            s_off[tid * 8 + k]     = min(rmin + k, Hn - 1) * (Wn * Cn);
            s_off[tid * 8 + 4 + k] = min(cmin + k, Wn - 1) * Cn;
        }
    }
    __syncthreads();

    // ---- gather: thread = (bin slice bs) x (channel quad c4 within half) ----
    const int c4 = tid & 31;        // channels half*128 + 4*c4 .. +3
    const int bs = tid >> 5;        // bin slice 0..7
    const float* base = g_xt + (size_t)(bidx * Hn * Wn) * Cn + half * 128 + c4 * 4;

    for (int bin = bs; bin < 49; bin += 8) {
        const float4* wv = (const float4*)(s_w + bin * 16);
        const int4 ro = ((const int4*)(s_off + bin * 8))[0];
        const int4 co = ((const int4*)(s_off + bin * 8))[1];
        float ax = 0.f, ay = 0.f, az = 0.f, aw = 0.f;
        const int rr[4] = {ro.x, ro.y, ro.z, ro.w};
        const int cc[4] = {co.x, co.y, co.z, co.w};
#pragma unroll
        for (int r = 0; r < 4; r++) {
            const float4 w = wv[r];
            float4 v0 = *(const float4*)(base + rr[r] + cc[0]);
            float4 v1 = *(const float4*)(base + rr[r] + cc[1]);
            float4 v2 = *(const float4*)(base + rr[r] + cc[2]);
            float4 v3 = *(const float4*)(base + rr[r] + cc[3]);
            ax = fmaf(w.x, v0.x, ax); ay = fmaf(w.x, v0.y, ay);
            az = fmaf(w.x, v0.z, az); aw = fmaf(w.x, v0.w, aw);
            ax = fmaf(w.y, v1.x, ax); ay = fmaf(w.y, v1.y, ay);
            az = fmaf(w.y, v1.z, az); aw = fmaf(w.y, v1.w, aw);
            ax = fmaf(w.z, v2.x, ax); ay = fmaf(w.z, v2.y, ay);
            az = fmaf(w.z, v2.z, az); aw = fmaf(w.z, v2.w, aw);
            ax = fmaf(w.w, v3.x, ax); ay = fmaf(w.w, v3.y, ay);
            az = fmaf(w.w, v3.z, az); aw = fmaf(w.w, v3.w, aw);
        }
        *(float4*)(s_out + bin * SOUT_PITCH + c4 * 4) = make_float4(ax, ay, az, aw);
    }
    __syncthreads();

    // ---- coalesced store of this half's contiguous [128][49] chunk ----
    float* o = out + (size_t)n * (Cn * 49) + half * (128 * 49);
    for (int l = tid; l < 128 * 49; l += 256) {
        const int c = l / 49;
        const int bin = l - c * 49;
        o[l] = s_out[bin * SOUT_PITCH + c];
    }
}

extern "C" void kernel_launch(void* const* d_in, const int* in_sizes, int n_in,
                              void* d_out, int out_size) {
    const float* x      = (const float*)d_in[0];
    const float* rois   = (const float*)d_in[1];
    const float* offset = (const float*)d_in[2];
    float* out = (float*)d_out;

    // NCHW -> NHWC
    dim3 tgrid(Wn / 32, Cn / 128, Bn * Hn);
    transpose_nchw_nhwc<<<tgrid, 256>>>(x);

    const int smem_bytes = (49 * SOUT_PITCH + 49 * 16) * sizeof(float) + 49 * 8 * sizeof(int);
    dcn_pool_kernel<<<dim3(N_ROIS, 2), 256, smem_bytes>>>(rois, offset, out);
}

// round 4
// speedup vs baseline: 2.3597x; 2.3597x over previous
#include <cuda_runtime.h>

#define Bn 4
#define Cn 256
#define Hn 128
#define Wn 128
#define N_ROIS 512
#define Pn 7
#define SCALE_F 0.0625f
#define GAMMA_F 0.1f

// NHWC scratch: [B, H, W, C] = 16,777,216 floats (64 MB)
__device__ float g_xt[Bn * Hn * Wn * Cn];

// ---------------------------------------------------------------------------
// NCHW -> NHWC transpose, float4 both directions.
// ---------------------------------------------------------------------------
__global__ void __launch_bounds__(256) transpose_nchw_nhwc(const float* __restrict__ x) {
    __shared__ float tile[32][33];
    const int bhy = blockIdx.z;          // b*H + y
    const int b = bhy >> 7;
    const int y = bhy & 127;
    const int w0 = blockIdx.x * 32;
    const int tid = threadIdx.x;

    const int cl = tid >> 3;             // 0..31 channel row (load)
    const int w4 = (tid & 7) * 4;        // 0..28 w quad (load)
    const int wl = tid >> 3;             // 0..31 w (store)
    const int c4 = (tid & 7) * 4;        // 0..28 c quad (store)

#pragma unroll
    for (int ct = 0; ct < 4; ct++) {
        const int c0 = blockIdx.y * 128 + ct * 32;
        const float4 v = *(const float4*)(x + (((size_t)(b * Cn + c0 + cl) * Hn + y) * Wn + w0 + w4));
        tile[cl][w4 + 0] = v.x;
        tile[cl][w4 + 1] = v.y;
        tile[cl][w4 + 2] = v.z;
        tile[cl][w4 + 3] = v.w;
        __syncthreads();
        float4 o;
        o.x = tile[c4 + 0][wl];
        o.y = tile[c4 + 1][wl];
        o.z = tile[c4 + 2][wl];
        o.w = tile[c4 + 3][wl];
        *(float4*)(g_xt + ((size_t)(bhy * Wn + w0 + wl) * Cn + c0 + c4)) = o;
        __syncthreads();
    }
}

// ---------------------------------------------------------------------------
// Deformable ROI pool. One block per ROI, 256 threads.
// Thread = (bin-slice bs = tid>>6) x (channel-quad c4 = tid&63).
// smem 57.2KB -> exactly 3 CTAs/SM -> ~57KB L1D carveout (critical for
// inter-bin patch reuse). Bin loop unrolled x2 for doubled MLP.
// ---------------------------------------------------------------------------
#define SOUT_PITCH 260   // 16B-aligned rows, stride-4-bank on copy-out (8-way ok)

__device__ __forceinline__ void gather_bin(
    const float* __restrict__ base,
    const float* __restrict__ s_w,
    const int*   __restrict__ s_off,
    int bin, float4& acc)
{
    const float4* wv = (const float4*)(s_w + bin * 16);
    const int4 ro = ((const int4*)(s_off + bin * 8))[0];
    const int4 co = ((const int4*)(s_off + bin * 8))[1];
    const int rr[4] = {ro.x, ro.y, ro.z, ro.w};
    const int cc[4] = {co.x, co.y, co.z, co.w};
    float ax = 0.f, ay = 0.f, az = 0.f, aw = 0.f;
#pragma unroll
    for (int r = 0; r < 4; r++) {
        const float4 w = wv[r];
        float4 v0 = *(const float4*)(base + rr[r] + cc[0]);
        float4 v1 = *(const float4*)(base + rr[r] + cc[1]);
        float4 v2 = *(const float4*)(base + rr[r] + cc[2]);
        float4 v3 = *(const float4*)(base + rr[r] + cc[3]);
        ax = fmaf(w.x, v0.x, ax); ay = fmaf(w.x, v0.y, ay);
        az = fmaf(w.x, v0.z, az); aw = fmaf(w.x, v0.w, aw);
        ax = fmaf(w.y, v1.x, ax); ay = fmaf(w.y, v1.y, ay);
        az = fmaf(w.y, v1.z, az); aw = fmaf(w.y, v1.w, aw);
        ax = fmaf(w.z, v2.x, ax); ay = fmaf(w.z, v2.y, ay);
        az = fmaf(w.z, v2.z, az); aw = fmaf(w.z, v2.w, aw);
        ax = fmaf(w.w, v3.x, ax); ay = fmaf(w.w, v3.y, ay);
        az = fmaf(w.w, v3.z, az); aw = fmaf(w.w, v3.w, aw);
    }
    acc = make_float4(ax, ay, az, aw);
}

__global__ void __launch_bounds__(256, 3) dcn_pool_kernel(
    const float* __restrict__ rois,
    const float* __restrict__ offset,
    float* __restrict__ out)
{
    extern __shared__ float smem[];
    float* s_out = smem;                           // 49*260 = 12740
    float* s_w   = smem + 49 * SOUT_PITCH;         // 49*16  = 784
    int*   s_off = (int*)(s_w + 49 * 16);          // 49*8   = 392

    const int n = blockIdx.x;
    const int tid = threadIdx.x;

    const int bidx = (int)rois[n * 5 + 0];

    if (tid < 49) {
        const float x1 = rois[n * 5 + 1] * SCALE_F - 0.5f;
        const float y1 = rois[n * 5 + 2] * SCALE_F - 0.5f;
        const float x2 = rois[n * 5 + 3] * SCALE_F - 0.5f;
        const float y2 = rois[n * 5 + 4] * SCALE_F - 0.5f;
        const float rw = fmaxf(x2 - x1, 1.0f);
        const float rh = fmaxf(y2 - y1, 1.0f);
        const float bw = rw * (1.0f / Pn);
        const float bh = rh * (1.0f / Pn);

        const int ph = tid / 7;
        const int pw = tid - ph * 7;
        const float ox = offset[n * 98 + tid];
        const float oy = offset[n * 98 + 49 + tid];
        const float ybase = y1 + (float)ph * bh + GAMMA_F * rh * oy;
        const float xbase = x1 + (float)pw * bw + GAMMA_F * rw * ox;

        // ---- y direction: 4 samples -> weights over 4 contiguous rows ----
        float wy[4] = {0.f, 0.f, 0.f, 0.f};
        int   y0a[4];
        float lya[4], va[4];
        int rmin = Hn;
#pragma unroll
        for (int i = 0; i < 4; i++) {
            const float s  = ((float)i + 0.5f) * 0.25f;
            const float ys = ybase + s * bh;
            const float v  = (ys > -1.0f && ys < (float)Hn) ? 0.25f : 0.0f;
            const float yc = fminf(fmaxf(ys, 0.0f), (float)(Hn - 1));
            const int   y0 = (int)yc;
            y0a[i] = y0; lya[i] = yc - (float)y0; va[i] = v;
            rmin = min(rmin, y0);
        }
#pragma unroll
        for (int i = 0; i < 4; i++) {
            const int sl0 = min(y0a[i] - rmin, 3);
            const int sl1 = min(min(y0a[i] + 1, Hn - 1) - rmin, 3);
            wy[sl0] += (1.0f - lya[i]) * va[i];
            wy[sl1] += lya[i] * va[i];
        }

        // ---- x direction ----
        float wx[4] = {0.f, 0.f, 0.f, 0.f};
        int   x0a[4];
        float lxa[4], vxa[4];
        int cmin = Wn;
#pragma unroll
        for (int j = 0; j < 4; j++) {
            const float s  = ((float)j + 0.5f) * 0.25f;
            const float xs = xbase + s * bw;
            const float v  = (xs > -1.0f && xs < (float)Wn) ? 0.25f : 0.0f;
            const float xc = fminf(fmaxf(xs, 0.0f), (float)(Wn - 1));
            const int   x0 = (int)xc;
            x0a[j] = x0; lxa[j] = xc - (float)x0; vxa[j] = v;
            cmin = min(cmin, x0);
        }
#pragma unroll
        for (int j = 0; j < 4; j++) {
            const int sl0 = min(x0a[j] - cmin, 3);
            const int sl1 = min(min(x0a[j] + 1, Wn - 1) - cmin, 3);
            wx[sl0] += (1.0f - lxa[j]) * vxa[j];
            wx[sl1] += lxa[j] * vxa[j];
        }

        // ---- weights (16) + row/col offsets (4+4) ----
#pragma unroll
        for (int r = 0; r < 4; r++)
#pragma unroll
            for (int q = 0; q < 4; q++)
                s_w[tid * 16 + r * 4 + q] = wy[r] * wx[q];
#pragma unroll
        for (int k = 0; k < 4; k++) {
            s_off[tid * 8 + k]     = min(rmin + k, Hn - 1) * (Wn * Cn);
            s_off[tid * 8 + 4 + k] = min(cmin + k, Wn - 1) * Cn;
        }
    }
    __syncthreads();

    // ---- gather: thread = (bin slice bs 0..3) x (channel quad c4 0..63) ----
    const int c4 = tid & 63;
    const int bs = tid >> 6;
    const float* base = g_xt + (size_t)(bidx * Hn * Wn) * Cn + c4 * 4;
    float* sout_row = s_out + c4 * 4;

    // 2-bin unrolled: two independent gather chains in flight (double MLP)
    int bin = bs;
    for (; bin + 4 < 49; bin += 8) {
        float4 accA, accB;
        gather_bin(base, s_w, s_off, bin,     accA);
        gather_bin(base, s_w, s_off, bin + 4, accB);
        *(float4*)(sout_row + bin       * SOUT_PITCH) = accA;
        *(float4*)(sout_row + (bin + 4) * SOUT_PITCH) = accB;
    }
    if (bin < 49) {
        float4 accA;
        gather_bin(base, s_w, s_off, bin, accA);
        *(float4*)(sout_row + bin * SOUT_PITCH) = accA;
    }
    __syncthreads();

    // ---- coalesced store of the ROI's contiguous [C][49] output chunk ----
    float* o = out + (size_t)n * (Cn * 49);
#pragma unroll
    for (int i = 0; i < 49; i++) {
        const int l = i * 256 + tid;          // l = c*49 + bin
        const int c = l / 49;
        const int b = l - c * 49;
        o[l] = s_out[b * SOUT_PITCH + c];
    }
}

extern "C" void kernel_launch(void* const* d_in, const int* in_sizes, int n_in,
                              void* d_out, int out_size) {
    const float* x      = (const float*)d_in[0];
    const float* rois   = (const float*)d_in[1];
    const float* offset = (const float*)d_in[2];
    float* out = (float*)d_out;

    // NCHW -> NHWC
    dim3 tgrid(Wn / 32, Cn / 128, Bn * Hn);
    transpose_nchw_nhwc<<<tgrid, 256>>>(x);

    const int smem_bytes = (49 * SOUT_PITCH + 49 * 16) * sizeof(float) + 49 * 8 * sizeof(int);
    static bool attr_set = false;
    if (!attr_set) {
        cudaFuncSetAttribute(dcn_pool_kernel,
                             cudaFuncAttributeMaxDynamicSharedMemorySize, smem_bytes);
        attr_set = true;
    }
    dcn_pool_kernel<<<N_ROIS, 256, smem_bytes>>>(rois, offset, out);
}

// round 5
// speedup vs baseline: 2.5658x; 1.0873x over previous
#include <cuda_runtime.h>

#define Bn 4
#define Cn 256
#define Hn 128
#define Wn 128
#define N_ROIS 512
#define Pn 7
#define SCALE_F 0.0625f
#define GAMMA_F 0.1f

// NHWC scratch: [B, H, W, C] = 16,777,216 floats (64 MB)
__device__ float g_xt[Bn * Hn * Wn * Cn];

// ---------------------------------------------------------------------------
// NCHW -> NHWC transpose, float4 both directions. (HBM/LTS-bound, ~19.5us)
// ---------------------------------------------------------------------------
__global__ void __launch_bounds__(256) transpose_nchw_nhwc(const float* __restrict__ x) {
    __shared__ float tile[32][33];
    const int bhy = blockIdx.z;          // b*H + y
    const int b = bhy >> 7;
    const int y = bhy & 127;
    const int w0 = blockIdx.x * 32;
    const int tid = threadIdx.x;

    const int cl = tid >> 3;             // 0..31 channel row (load)
    const int w4 = (tid & 7) * 4;        // 0..28 w quad (load)
    const int wl = tid >> 3;             // 0..31 w (store)
    const int c4 = (tid & 7) * 4;        // 0..28 c quad (store)

#pragma unroll
    for (int ct = 0; ct < 4; ct++) {
        const int c0 = blockIdx.y * 128 + ct * 32;
        const float4 v = *(const float4*)(x + (((size_t)(b * Cn + c0 + cl) * Hn + y) * Wn + w0 + w4));
        tile[cl][w4 + 0] = v.x;
        tile[cl][w4 + 1] = v.y;
        tile[cl][w4 + 2] = v.z;
        tile[cl][w4 + 3] = v.w;
        __syncthreads();
        float4 o;
        o.x = tile[c4 + 0][wl];
        o.y = tile[c4 + 1][wl];
        o.z = tile[c4 + 2][wl];
        o.w = tile[c4 + 3][wl];
        *(float4*)(g_xt + ((size_t)(bhy * Wn + w0 + wl) * Cn + c0 + c4)) = o;
        __syncthreads();
    }
}

// ---------------------------------------------------------------------------
// Deformable ROI pool. One block per ROI, 512 threads.
// Thread = (bin-slice bs = tid>>6, 0..7) x (channel-quad c4 = tid&63).
// smem ~54.4KB x 2 CTAs/SM -> ~119KB L1D carveout + 32 warps/SM.
// 2-bin unroll keeps two independent gather chains in flight per thread.
// ---------------------------------------------------------------------------
#define SOUT_PITCH 260   // 16B-aligned rows

__device__ __forceinline__ void gather_bin(
    const float* __restrict__ base,
    const float* __restrict__ s_w,
    const int*   __restrict__ s_off,
    int bin, float4& acc)
{
    const float4* wv = (const float4*)(s_w + bin * 16);
    const int4 ro = ((const int4*)(s_off + bin * 8))[0];
    const int4 co = ((const int4*)(s_off + bin * 8))[1];
    const int rr[4] = {ro.x, ro.y, ro.z, ro.w};
    const int cc[4] = {co.x, co.y, co.z, co.w};
    float ax = 0.f, ay = 0.f, az = 0.f, aw = 0.f;
#pragma unroll
    for (int r = 0; r < 4; r++) {
        const float4 w = wv[r];
        float4 v0 = *(const float4*)(base + rr[r] + cc[0]);
        float4 v1 = *(const float4*)(base + rr[r] + cc[1]);
        float4 v2 = *(const float4*)(base + rr[r] + cc[2]);
        float4 v3 = *(const float4*)(base + rr[r] + cc[3]);
        ax = fmaf(w.x, v0.x, ax); ay = fmaf(w.x, v0.y, ay);
        az = fmaf(w.x, v0.z, az); aw = fmaf(w.x, v0.w, aw);
        ax = fmaf(w.y, v1.x, ax); ay = fmaf(w.y, v1.y, ay);
        az = fmaf(w.y, v1.z, az); aw = fmaf(w.y, v1.w, aw);
        ax = fmaf(w.z, v2.x, ax); ay = fmaf(w.z, v2.y, ay);
        az = fmaf(w.z, v2.z, az); aw = fmaf(w.z, v2.w, aw);
        ax = fmaf(w.w, v3.x, ax); ay = fmaf(w.w, v3.y, ay);
        az = fmaf(w.w, v3.z, az); aw = fmaf(w.w, v3.w, aw);
    }
    acc = make_float4(ax, ay, az, aw);
}

__global__ void __launch_bounds__(512, 2) dcn_pool_kernel(
    const float* __restrict__ rois,
    const float* __restrict__ offset,
    float* __restrict__ out)
{
    extern __shared__ float smem[];
    float* s_out = smem;                           // 49*260 = 12740
    float* s_w   = smem + 49 * SOUT_PITCH;         // 49*16  = 784
    int*   s_off = (int*)(s_w + 49 * 16);          // 49*8   = 392

    const int n = blockIdx.x;
    const int tid = threadIdx.x;

    const int bidx = (int)rois[n * 5 + 0];

    if (tid < 49) {
        const float x1 = rois[n * 5 + 1] * SCALE_F - 0.5f;
        const float y1 = rois[n * 5 + 2] * SCALE_F - 0.5f;
        const float x2 = rois[n * 5 + 3] * SCALE_F - 0.5f;
        const float y2 = rois[n * 5 + 4] * SCALE_F - 0.5f;
        const float rw = fmaxf(x2 - x1, 1.0f);
        const float rh = fmaxf(y2 - y1, 1.0f);
        const float bw = rw * (1.0f / Pn);
        const float bh = rh * (1.0f / Pn);

        const int ph = tid / 7;
        const int pw = tid - ph * 7;
        const float ox = offset[n * 98 + tid];
        const float oy = offset[n * 98 + 49 + tid];
        const float ybase = y1 + (float)ph * bh + GAMMA_F * rh * oy;
        const float xbase = x1 + (float)pw * bw + GAMMA_F * rw * ox;

        // ---- y direction: 4 samples -> weights over 4 contiguous rows ----
        float wy[4] = {0.f, 0.f, 0.f, 0.f};
        int   y0a[4];
        float lya[4], va[4];
        int rmin = Hn;
#pragma unroll
        for (int i = 0; i < 4; i++) {
            const float s  = ((float)i + 0.5f) * 0.25f;
            const float ys = ybase + s * bh;
            const float v  = (ys > -1.0f && ys < (float)Hn) ? 0.25f : 0.0f;
            const float yc = fminf(fmaxf(ys, 0.0f), (float)(Hn - 1));
            const int   y0 = (int)yc;
            y0a[i] = y0; lya[i] = yc - (float)y0; va[i] = v;
            rmin = min(rmin, y0);
        }
#pragma unroll
        for (int i = 0; i < 4; i++) {
            const int sl0 = min(y0a[i] - rmin, 3);
            const int sl1 = min(min(y0a[i] + 1, Hn - 1) - rmin, 3);
            wy[sl0] += (1.0f - lya[i]) * va[i];
            wy[sl1] += lya[i] * va[i];
        }

        // ---- x direction ----
        float wx[4] = {0.f, 0.f, 0.f, 0.f};
        int   x0a[4];
        float lxa[4], vxa[4];
        int cmin = Wn;
#pragma unroll
        for (int j = 0; j < 4; j++) {
            const float s  = ((float)j + 0.5f) * 0.25f;
            const float xs = xbase + s * bw;
            const float v  = (xs > -1.0f && xs < (float)Wn) ? 0.25f : 0.0f;
            const float xc = fminf(fmaxf(xs, 0.0f), (float)(Wn - 1));
            const int   x0 = (int)xc;
            x0a[j] = x0; lxa[j] = xc - (float)x0; vxa[j] = v;
            cmin = min(cmin, x0);
        }
#pragma unroll
        for (int j = 0; j < 4; j++) {
            const int sl0 = min(x0a[j] - cmin, 3);
            const int sl1 = min(min(x0a[j] + 1, Wn - 1) - cmin, 3);
            wx[sl0] += (1.0f - lxa[j]) * vxa[j];
            wx[sl1] += lxa[j] * vxa[j];
        }

        // ---- weights (16) + row/col offsets (4+4) ----
#pragma unroll
        for (int r = 0; r < 4; r++)
#pragma unroll
            for (int q = 0; q < 4; q++)
                s_w[tid * 16 + r * 4 + q] = wy[r] * wx[q];
#pragma unroll
        for (int k = 0; k < 4; k++) {
            s_off[tid * 8 + k]     = min(rmin + k, Hn - 1) * (Wn * Cn);
            s_off[tid * 8 + 4 + k] = min(cmin + k, Wn - 1) * Cn;
        }
    }
    __syncthreads();

    // ---- gather: thread = (bin slice bs 0..7) x (channel quad c4 0..63) ----
    const int c4 = tid & 63;
    const int bs = tid >> 6;
    const float* base = g_xt + (size_t)(bidx * Hn * Wn) * Cn + c4 * 4;
    float* sout_row = s_out + c4 * 4;

    // 2-bin unrolled: pairs (bin, bin+8), stride 16
    int bin = bs;
    for (; bin + 8 < 49; bin += 16) {
        float4 accA, accB;
        gather_bin(base, s_w, s_off, bin,     accA);
        gather_bin(base, s_w, s_off, bin + 8, accB);
        *(float4*)(sout_row + bin       * SOUT_PITCH) = accA;
        *(float4*)(sout_row + (bin + 8) * SOUT_PITCH) = accB;
    }
    if (bin < 49) {
        float4 accA;
        gather_bin(base, s_w, s_off, bin, accA);
        *(float4*)(sout_row + bin * SOUT_PITCH) = accA;
    }
    __syncthreads();

    // ---- coalesced store of the ROI's contiguous [C][49] output chunk ----
    float* o = out + (size_t)n * (Cn * 49);
    for (int l = tid; l < Cn * 49; l += 512) {
        const int c = l / 49;
        const int b = l - c * 49;
        o[l] = s_out[b * SOUT_PITCH + c];
    }
}

extern "C" void kernel_launch(void* const* d_in, const int* in_sizes, int n_in,
                              void* d_out, int out_size) {
    const float* x      = (const float*)d_in[0];
    const float* rois   = (const float*)d_in[1];
    const float* offset = (const float*)d_in[2];
    float* out = (float*)d_out;

    // NCHW -> NHWC
    dim3 tgrid(Wn / 32, Cn / 128, Bn * Hn);
    transpose_nchw_nhwc<<<tgrid, 256>>>(x);

    const int smem_bytes = (49 * SOUT_PITCH + 49 * 16) * sizeof(float) + 49 * 8 * sizeof(int);
    static bool attr_set = false;
    if (!attr_set) {
        cudaFuncSetAttribute(dcn_pool_kernel,
                             cudaFuncAttributeMaxDynamicSharedMemorySize, smem_bytes);
        attr_set = true;
    }
    dcn_pool_kernel<<<N_ROIS, 512, smem_bytes>>>(rois, offset, out);
}

// round 6
// speedup vs baseline: 2.5884x; 1.0088x over previous
#include <cuda_runtime.h>

#define Bn 4
#define Cn 256
#define Hn 128
#define Wn 128
#define N_ROIS 512
#define Pn 7
#define SCALE_F 0.0625f
#define GAMMA_F 0.1f

// NHWC scratch: [B, H, W, C] = 16,777,216 floats (64 MB)
__device__ float g_xt[Bn * Hn * Wn * Cn];

// ---------------------------------------------------------------------------
// NCHW -> NHWC transpose, float4 both directions. (HBM/LTS-bound, ~20us)
// ---------------------------------------------------------------------------
__global__ void __launch_bounds__(256) transpose_nchw_nhwc(const float* __restrict__ x) {
    __shared__ float tile[32][33];
    const int bhy = blockIdx.z;          // b*H + y
    const int b = bhy >> 7;
    const int y = bhy & 127;
    const int w0 = blockIdx.x * 32;
    const int tid = threadIdx.x;

    const int cl = tid >> 3;             // 0..31 channel row (load)
    const int w4 = (tid & 7) * 4;        // 0..28 w quad (load)
    const int wl = tid >> 3;             // 0..31 w (store)
    const int c4 = (tid & 7) * 4;        // 0..28 c quad (store)

#pragma unroll
    for (int ct = 0; ct < 4; ct++) {
        const int c0 = blockIdx.y * 128 + ct * 32;
        const float4 v = *(const float4*)(x + (((size_t)(b * Cn + c0 + cl) * Hn + y) * Wn + w0 + w4));
        tile[cl][w4 + 0] = v.x;
        tile[cl][w4 + 1] = v.y;
        tile[cl][w4 + 2] = v.z;
        tile[cl][w4 + 3] = v.w;
        __syncthreads();
        float4 o;
        o.x = tile[c4 + 0][wl];
        o.y = tile[c4 + 1][wl];
        o.z = tile[c4 + 2][wl];
        o.w = tile[c4 + 3][wl];
        *(float4*)(g_xt + ((size_t)(bhy * Wn + w0 + wl) * Cn + c0 + c4)) = o;
        __syncthreads();
    }
}

// ---------------------------------------------------------------------------
// Deformable ROI pool. One block per ROI, 512 threads.
// Thread = (bin-slice bs = tid>>6, 0..7) x (channel-quad c4 = tid&63).
// Per-bin 64B record in smem: wy[4], wx[4], row_off[4], col_off[4].
// Warp-uniform zero-weight skipping: whole warp shares a bin, so wy[r]==0 /
// wx[q]==0 branches have no divergence -> ~40% fewer gather loads.
// ---------------------------------------------------------------------------
#define SOUT_PITCH 260   // 16B-aligned rows

__device__ __forceinline__ void gather_bin(
    const float* __restrict__ base,
    const float* __restrict__ s_bin,
    int bin, float4& acc)
{
    const float* rec = s_bin + bin * 16;
    const float4 wy4 = *(const float4*)(rec);
    const float4 wx4 = *(const float4*)(rec + 4);
    const int4   ro4 = *(const int4*)(rec + 8);
    const int4   co4 = *(const int4*)(rec + 12);
    const float wyA[4] = {wy4.x, wy4.y, wy4.z, wy4.w};
    const float wxA[4] = {wx4.x, wx4.y, wx4.z, wx4.w};
    const int   roA[4] = {ro4.x, ro4.y, ro4.z, ro4.w};
    const int   coA[4] = {co4.x, co4.y, co4.z, co4.w};

    float ax = 0.f, ay = 0.f, az = 0.f, aw = 0.f;
#pragma unroll
    for (int r = 0; r < 4; r++) {
        const float wr = wyA[r];
        if (wr != 0.0f) {                      // warp-uniform branch
            const float* rp = base + roA[r];
#pragma unroll
            for (int q = 0; q < 4; q++) {
                const float wq = wxA[q];
                if (wq != 0.0f) {              // warp-uniform branch
                    const float w = wr * wq;
                    const float4 v = *(const float4*)(rp + coA[q]);
                    ax = fmaf(w, v.x, ax);
                    ay = fmaf(w, v.y, ay);
                    az = fmaf(w, v.z, az);
                    aw = fmaf(w, v.w, aw);
                }
            }
        }
    }
    acc = make_float4(ax, ay, az, aw);
}

__global__ void __launch_bounds__(512, 2) dcn_pool_kernel(
    const float* __restrict__ rois,
    const float* __restrict__ offset,
    float* __restrict__ out)
{
    extern __shared__ float smem[];
    float* s_out = smem;                           // 49*260 = 12740 floats
    float* s_bin = smem + 49 * SOUT_PITCH;         // 49*16  = 784 floats

    const int n = blockIdx.x;
    const int tid = threadIdx.x;

    const int bidx = (int)rois[n * 5 + 0];

    if (tid < 49) {
        const float x1 = rois[n * 5 + 1] * SCALE_F - 0.5f;
        const float y1 = rois[n * 5 + 2] * SCALE_F - 0.5f;
        const float x2 = rois[n * 5 + 3] * SCALE_F - 0.5f;
        const float y2 = rois[n * 5 + 4] * SCALE_F - 0.5f;
        const float rw = fmaxf(x2 - x1, 1.0f);
        const float rh = fmaxf(y2 - y1, 1.0f);
        const float bw = rw * (1.0f / Pn);
        const float bh = rh * (1.0f / Pn);

        const int ph = tid / 7;
        const int pw = tid - ph * 7;
        const float ox = offset[n * 98 + tid];
        const float oy = offset[n * 98 + 49 + tid];
        const float ybase = y1 + (float)ph * bh + GAMMA_F * rh * oy;
        const float xbase = x1 + (float)pw * bw + GAMMA_F * rw * ox;

        // ---- y direction: 4 samples -> weights over 4 contiguous rows ----
        float wy[4] = {0.f, 0.f, 0.f, 0.f};
        int   y0a[4];
        float lya[4], va[4];
        int rmin = Hn;
#pragma unroll
        for (int i = 0; i < 4; i++) {
            const float s  = ((float)i + 0.5f) * 0.25f;
            const float ys = ybase + s * bh;
            const float v  = (ys > -1.0f && ys < (float)Hn) ? 0.25f : 0.0f;
            const float yc = fminf(fmaxf(ys, 0.0f), (float)(Hn - 1));
            const int   y0 = (int)yc;
            y0a[i] = y0; lya[i] = yc - (float)y0; va[i] = v;
            rmin = min(rmin, y0);
        }
#pragma unroll
        for (int i = 0; i < 4; i++) {
            const int sl0 = min(y0a[i] - rmin, 3);
            const int sl1 = min(min(y0a[i] + 1, Hn - 1) - rmin, 3);
            wy[sl0] += (1.0f - lya[i]) * va[i];
            wy[sl1] += lya[i] * va[i];
        }

        // ---- x direction ----
        float wx[4] = {0.f, 0.f, 0.f, 0.f};
        int   x0a[4];
        float lxa[4], vxa[4];
        int cmin = Wn;
#pragma unroll
        for (int j = 0; j < 4; j++) {
            const float s  = ((float)j + 0.5f) * 0.25f;
            const float xs = xbase + s * bw;
            const float v  = (xs > -1.0f && xs < (float)Wn) ? 0.25f : 0.0f;
            const float xc = fminf(fmaxf(xs, 0.0f), (float)(Wn - 1));
            const int   x0 = (int)xc;
            x0a[j] = x0; lxa[j] = xc - (float)x0; vxa[j] = v;
            cmin = min(cmin, x0);
        }
#pragma unroll
        for (int j = 0; j < 4; j++) {
            const int sl0 = min(x0a[j] - cmin, 3);
            const int sl1 = min(min(x0a[j] + 1, Wn - 1) - cmin, 3);
            wx[sl0] += (1.0f - lxa[j]) * vxa[j];
            wx[sl1] += lxa[j] * vxa[j];
        }

        // ---- per-bin record: wy[4] | wx[4] | ro[4] | co[4] ----
        float* rec = s_bin + tid * 16;
#pragma unroll
        for (int k = 0; k < 4; k++) {
            rec[k]     = wy[k];
            rec[4 + k] = wx[k];
            ((int*)rec)[8 + k]  = min(rmin + k, Hn - 1) * (Wn * Cn);
            ((int*)rec)[12 + k] = min(cmin + k, Wn - 1) * Cn;
        }
    }
    __syncthreads();

    // ---- gather: thread = (bin slice bs 0..7) x (channel quad c4 0..63) ----
    const int c4 = tid & 63;
    const int bs = tid >> 6;
    const float* base = g_xt + (size_t)(bidx * Hn * Wn) * Cn + c4 * 4;
    float* sout_row = s_out + c4 * 4;

    // 2-bin unrolled: pairs (bin, bin+8), stride 16 (two chains in flight)
    int bin = bs;
    for (; bin + 8 < 49; bin += 16) {
        float4 accA, accB;
        gather_bin(base, s_bin, bin,     accA);
        gather_bin(base, s_bin, bin + 8, accB);
        *(float4*)(sout_row + bin       * SOUT_PITCH) = accA;
        *(float4*)(sout_row + (bin + 8) * SOUT_PITCH) = accB;
    }
    if (bin < 49) {
        float4 accA;
        gather_bin(base, s_bin, bin, accA);
        *(float4*)(sout_row + bin * SOUT_PITCH) = accA;
    }
    __syncthreads();

    // ---- coalesced store of the ROI's contiguous [C][49] output chunk ----
    float* o = out + (size_t)n * (Cn * 49);
    for (int l = tid; l < Cn * 49; l += 512) {
        const int c = l / 49;
        const int b = l - c * 49;
        o[l] = s_out[b * SOUT_PITCH + c];
    }
}

extern "C" void kernel_launch(void* const* d_in, const int* in_sizes, int n_in,
                              void* d_out, int out_size) {
    const float* x      = (const float*)d_in[0];
    const float* rois   = (const float*)d_in[1];
    const float* offset = (const float*)d_in[2];
    float* out = (float*)d_out;

    // NCHW -> NHWC
    dim3 tgrid(Wn / 32, Cn / 128, Bn * Hn);
    transpose_nchw_nhwc<<<tgrid, 256>>>(x);

    const int smem_bytes = (49 * SOUT_PITCH + 49 * 16) * sizeof(float);
    static bool attr_set = false;
    if (!attr_set) {
        cudaFuncSetAttribute(dcn_pool_kernel,
                             cudaFuncAttributeMaxDynamicSharedMemorySize, smem_bytes);
        attr_set = true;
    }
    dcn_pool_kernel<<<N_ROIS, 512, smem_bytes>>>(rois, offset, out);
}